// round 13
// baseline (speedup 1.0000x reference)
#include <cuda_runtime.h>
#include <cuda_fp16.h>
#include <math.h>
#include <stdint.h>

// ---------------- problem constants ----------------
#define NB 2
#define NT 2048
#define NC 2048
#define NH 16
#define ND 128
#define C3 (3 * NC)      /* 6144 */
#define BT (NB * NT)     /* 4096 */

#define RMS_EPS 1.1920929e-07f
#define SM_SCALE (1.0f / 128.0f)

// ---------------- scratch ----------------
__device__ __half g_qkv16[(size_t)BT * C3];        // fp16 qkv straight from GEMM
__device__ __half g_x16[(size_t)BT * NC];          // x fp16
__device__ __half g_wqkvT16[(size_t)C3 * NC];      // w_qkv^T fp16
__device__ __half g_wprojT16[(size_t)NC * NC];     // w_proj^T fp16
__device__ __half g_qk16[(size_t)BT * 2 * NC];     // normed+roped q,k fp16
__device__ __half g_y16[(size_t)BT * NC];          // attention out fp16
__device__ float g_cos[NT * 64];
__device__ float g_sin[NT * 64];

// ---------------- helpers ----------------
__device__ __forceinline__ void mma_f16(float c[4],
                                        uint32_t a0, uint32_t a1, uint32_t a2, uint32_t a3,
                                        uint32_t b0, uint32_t b1) {
    asm volatile(
        "mma.sync.aligned.m16n8k16.row.col.f32.f16.f16.f32 "
        "{%0,%1,%2,%3}, {%4,%5,%6,%7}, {%8,%9}, {%0,%1,%2,%3};"
        : "+f"(c[0]), "+f"(c[1]), "+f"(c[2]), "+f"(c[3])
        : "r"(a0), "r"(a1), "r"(a2), "r"(a3), "r"(b0), "r"(b1));
}

__device__ __forceinline__ void ldsm_x4(uint32_t& r0, uint32_t& r1,
                                        uint32_t& r2, uint32_t& r3, uint32_t addr) {
    asm volatile("ldmatrix.sync.aligned.m8n8.x4.shared.b16 {%0,%1,%2,%3}, [%4];"
        : "=r"(r0), "=r"(r1), "=r"(r2), "=r"(r3) : "r"(addr));
}

__device__ __forceinline__ void ldsm_x4_trans(uint32_t& r0, uint32_t& r1,
                                              uint32_t& r2, uint32_t& r3, uint32_t addr) {
    asm volatile("ldmatrix.sync.aligned.m8n8.x4.trans.shared.b16 {%0,%1,%2,%3}, [%4];"
        : "=r"(r0), "=r"(r1), "=r"(r2), "=r"(r3) : "r"(addr));
}

__device__ __forceinline__ uint32_t smem_u32(const void* p) {
    uint32_t a;
    asm("{ .reg .u64 t; cvta.to.shared.u64 t, %1; cvt.u32.u64 %0, t; }"
        : "=r"(a) : "l"(p));
    return a;
}

__device__ __forceinline__ void cp_async16(uint32_t dst, const void* src) {
    asm volatile("cp.async.cg.shared.global [%0], [%1], 16;" :: "r"(dst), "l"(src));
}
#define CP_COMMIT() asm volatile("cp.async.commit_group;" ::: "memory")
#define CP_WAIT0()  asm volatile("cp.async.wait_group 0;" ::: "memory")
#define CP_WAIT1()  asm volatile("cp.async.wait_group 1;" ::: "memory")

// ============================================================
// RoPE tables
// ============================================================
__global__ void rope_tables_kernel() {
    int idx = blockIdx.x * blockDim.x + threadIdx.x;
    if (idx >= NT * 64) return;
    int t = idx >> 6;
    int i = idx & 63;
    double inv_f = exp(-((double)i / 64.0) * log(1.0e6));
    double ang = (double)t * inv_f;
    g_cos[idx] = (float)cos(ang);
    g_sin[idx] = (float)sin(ang);
}

// ============================================================
// fp32 -> fp16 copy
// ============================================================
__global__ __launch_bounds__(256) void cvt16_kernel(
    const float4* __restrict__ in, uint2* __restrict__ out, int n4)
{
    int i = blockIdx.x * blockDim.x + threadIdx.x;
    if (i >= n4) return;
    float4 v = in[i];
    __half2 lo = __floats2half2_rn(v.x, v.y);
    __half2 hi = __floats2half2_rn(v.z, v.w);
    uint2 p;
    p.x = *(uint32_t*)&lo;
    p.y = *(uint32_t*)&hi;
    out[i] = p;
}

// ============================================================
// Transpose -> fp16
// ============================================================
__global__ __launch_bounds__(256) void transpose16_kernel(
    const float* __restrict__ in, __half* __restrict__ out, int R, int Ccols)
{
    __shared__ float tile[32][33];
    int c0 = blockIdx.x * 32, r0 = blockIdx.y * 32;
    int tx = threadIdx.x, ty = threadIdx.y;
#pragma unroll
    for (int j = 0; j < 32; j += 8)
        tile[ty + j][tx] = in[(size_t)(r0 + ty + j) * Ccols + c0 + tx];
    __syncthreads();
#pragma unroll
    for (int j = 0; j < 32; j += 8)
        out[(size_t)(c0 + ty + j) * R + r0 + tx] = __float2half_rn(tile[tx][ty + j]);
}

// ============================================================
// fp16 mma GEMM v2: C = A[M,K] @ Bt[N,K]^T.
// Block 128x256, BK=32, 512 thr = 16 warps (4m x 4n),
// warp tile 32x64, 3-stage cp.async, ldmatrix frags.
// HALF_OUT: fp16 epilogue (half2) vs fp32 (float2).
// smem/stage: A 128*80 + B 256*80 = 30720 B.
// ============================================================
#define GB_STG_BYTES 30720
#define GB_SMEM_BYTES (3 * GB_STG_BYTES)

template <bool HALF_OUT>
__global__ __launch_bounds__(512, 1) void gemm_f16_kernel(
    const __half* __restrict__ A, const __half* __restrict__ Bt,
    void* __restrict__ Cm, int K, int ldC, int c0off)
{
    extern __shared__ float sm[];
    const uint32_t smb = smem_u32(sm);

    const int tid = threadIdx.x;
    const int wid = tid >> 5;
    const int lane = tid & 31;
    const int gid = lane >> 2;
    const int tig = lane & 3;
    const int wm = wid & 3;          // 4 m-warps, 32 rows each
    const int wn = wid >> 2;         // 4 n-warps, 64 cols each
    const int m0 = blockIdx.y << 7;
    const int n0 = blockIdx.x << 8;

    const int mbase = wm << 5;
    const int nbase = wn << 6;

    const int la16 = lane & 15;
    const int lha = lane >> 4;
    const int lb8 = lane & 7;
    const int lbg = (lane >> 4) & 1;
    const int lbh = (lane >> 3) & 1;

    uint32_t aoff[2], boff[4];
#pragma unroll
    for (int mf = 0; mf < 2; mf++)
        aoff[mf] = (uint32_t)((mbase + (mf << 4) + la16) * 80 + lha * 16);
#pragma unroll
    for (int g = 0; g < 4; g++)
        boff[g] = 10240u + (uint32_t)((nbase + (g << 4) + lb8 + (lbg << 3)) * 80 + lbh * 16);

    float acc[2][8][4];
#pragma unroll
    for (int i = 0; i < 2; i++)
#pragma unroll
        for (int j = 0; j < 8; j++)
#pragma unroll
            for (int e = 0; e < 4; e++) acc[i][j][e] = 0.0f;

    const int nt = K >> 5;

    // A: 128 rows x 4 16B-segs = 512 -> 1/thread.
    // B: 256 rows x 4 segs = 1024 -> 2/thread.
#define GB_ISSUE(t_)                                                          \
    do {                                                                      \
        const int _k0 = (t_) << 5;                                            \
        const uint32_t _sb = smb + ((t_) % 3) * GB_STG_BYTES;                 \
        {                                                                     \
            int _r = tid >> 2, _s = tid & 3;                                  \
            cp_async16(_sb + _r * 80 + _s * 16,                               \
                (const char*)A + (((size_t)(m0 + _r) * K + _k0) << 1) + _s * 16); \
        }                                                                     \
        _Pragma("unroll")                                                     \
        for (int _i = 0; _i < 2; _i++) {                                      \
            int _f = tid + (_i << 9);                                         \
            int _r = _f >> 2, _s = _f & 3;                                    \
            cp_async16(_sb + 10240 + _r * 80 + _s * 16,                       \
                (const char*)Bt + (((size_t)(n0 + _r) * K + _k0) << 1) + _s * 16); \
        }                                                                     \
    } while (0)

    GB_ISSUE(0); CP_COMMIT();
    GB_ISSUE(1); CP_COMMIT();

    for (int t = 0; t < nt; t++) {
        CP_WAIT1();
        __syncthreads();
        if (t + 2 < nt) GB_ISSUE(t + 2);
        CP_COMMIT();

        const uint32_t sb = smb + (t % 3) * GB_STG_BYTES;
#pragma unroll
        for (int c = 0; c < 2; c++) {
            const uint32_t cb = (uint32_t)(c << 5);
            uint32_t af[2][4];
#pragma unroll
            for (int mf = 0; mf < 2; mf++)
                ldsm_x4(af[mf][0], af[mf][1], af[mf][2], af[mf][3],
                        sb + aoff[mf] + cb);
            uint32_t bf[8][2];
#pragma unroll
            for (int g = 0; g < 4; g++) {
                uint32_t b0, b1, b2, b3;
                ldsm_x4(b0, b1, b2, b3, sb + boff[g] + cb);
                bf[2 * g][0] = b0; bf[2 * g][1] = b1;
                bf[2 * g + 1][0] = b2; bf[2 * g + 1][1] = b3;
            }
#pragma unroll
            for (int mf = 0; mf < 2; mf++)
#pragma unroll
                for (int nf = 0; nf < 8; nf++)
                    mma_f16(acc[mf][nf], af[mf][0], af[mf][1], af[mf][2], af[mf][3],
                            bf[nf][0], bf[nf][1]);
        }
    }
#undef GB_ISSUE

#pragma unroll
    for (int mf = 0; mf < 2; mf++) {
#pragma unroll
        for (int nf = 0; nf < 8; nf++) {
            int r0_ = m0 + mbase + (mf << 4) + gid;
            int c = c0off + n0 + nbase + (nf << 3) + (tig << 1);
            if (HALF_OUT) {
                __half* C = (__half*)Cm;
                *(__half2*)&C[(size_t)r0_ * ldC + c] =
                    __floats2half2_rn(acc[mf][nf][0], acc[mf][nf][1]);
                *(__half2*)&C[(size_t)(r0_ + 8) * ldC + c] =
                    __floats2half2_rn(acc[mf][nf][2], acc[mf][nf][3]);
            } else {
                float* C = (float*)Cm;
                *(float2*)&C[(size_t)r0_ * ldC + c] =
                    make_float2(acc[mf][nf][0], acc[mf][nf][1]);
                *(float2*)&C[(size_t)(r0_ + 8) * ldC + c] =
                    make_float2(acc[mf][nf][2], acc[mf][nf][3]);
            }
        }
    }
}

// ============================================================
// RMSNorm + RoPE: fp16 q,k in g_qkv16 -> fp16 g_qk16.
// v untouched (flash reads it from g_qkv16 directly).
// ============================================================
__global__ __launch_bounds__(256) void rmsrope_kernel(
    const float* __restrict__ qw, const float* __restrict__ kw)
{
    const int tok = blockIdx.x;
    const int t = tok & (NT - 1);
    const int warp = threadIdx.x >> 5;
    const int lane = threadIdx.x & 31;

    const float c0 = g_cos[t * 64 + lane];
    const float s0 = g_sin[t * 64 + lane];
    const float c1 = g_cos[t * 64 + 32 + lane];
    const float s1 = g_sin[t * 64 + 32 + lane];

#pragma unroll
    for (int s = 0; s < 4; s++) {
        int task = warp + (s << 3);
        int isK = task >> 4;
        int h = task & 15;
        const float* w = isK ? kw : qw;
        const __half* src = g_qkv16 + (size_t)tok * C3 + (size_t)isK * 2048 + (size_t)h * ND;

        float x0 = __half2float(src[lane]);
        float x1 = __half2float(src[lane + 32]);
        float x2 = __half2float(src[lane + 64]);
        float x3 = __half2float(src[lane + 96]);

        float ss = x0 * x0 + x1 * x1 + x2 * x2 + x3 * x3;
#pragma unroll
        for (int off = 16; off > 0; off >>= 1)
            ss += __shfl_xor_sync(0xffffffffu, ss, off);
        float inv = 1.0f / sqrtf(ss * (1.0f / (float)ND) + RMS_EPS);

        float n0 = x0 * inv * w[lane];
        float n1 = x1 * inv * w[lane + 32];
        float n2 = x2 * inv * w[lane + 64];
        float n3 = x3 * inv * w[lane + 96];

        __half* dst = g_qk16 + ((size_t)tok * 2 + isK) * 2048 + h * ND;
        dst[lane]      = __float2half_rn(n0 * c0 - n2 * s0);
        dst[lane + 32] = __float2half_rn(n1 * c1 - n3 * s1);
        dst[lane + 64] = __float2half_rn(n2 * c0 + n0 * s0);
        dst[lane + 96] = __float2half_rn(n3 * c1 + n1 * s1);
    }
}

// ============================================================
// Flash attention, all-fp16 MMA (unchanged from R11 except
// V source = g_qkv16 with row stride C3).
// ============================================================
#define FB_Q     0
#define FB_STG   34816
#define FB_K(s)  (17408 + (s) * FB_STG)
#define FB_V(s)  (17408 + (s) * FB_STG + 17408)
#define FB_P     87040
#define FB_RM    96256
#define FB_RS    96768
#define FB_SMEM_BYTES 97280

__global__ __launch_bounds__(256, 2) void flash_mma_kernel()
{
    extern __shared__ float sm[];
    char* smc = (char*)sm;
    const uint32_t smb = smem_u32(sm);

    const int tid = threadIdx.x;
    const int lane = tid & 31;
    const int wid = tid >> 5;
    const int gid = lane >> 2;
    const int tig = lane & 3;
    const int wm = wid & 3;
    const int wn = wid >> 2;
    const int mbase = wm << 4;

    const int qb = (int)gridDim.x - 1 - (int)blockIdx.x;
    const int bh = blockIdx.y;
    const int b = bh >> 4;
    const int h = bh & 15;
    const int q0 = qb << 6;

    const int la16 = lane & 15;
    const int lha = lane >> 4;
    const int lb8 = lane & 7;
    const int lbg = (lane >> 4) & 1;
    const int lbh = (lane >> 3) & 1;

    const uint32_t qoff = smb + FB_Q + (uint32_t)((mbase + la16) * 272 + lha * 16);
    uint32_t koff[2];
#pragma unroll
    for (int g = 0; g < 2; g++)
        koff[g] = (uint32_t)(((wn << 5) + (g << 4) + lb8 + (lbg << 3)) * 272 + lbh * 16);

    const uint32_t poff = smb + FB_P + (uint32_t)((mbase + la16) * 144 + lha * 16);

    const int vlk = (lane & 7) + (((lane >> 3) & 1) << 3);
    const int vln = ((lane >> 4) & 1) << 3;
    uint32_t voff[4];
#pragma unroll
    for (int g = 0; g < 4; g++)
        voff[g] = (uint32_t)(vlk * 272 + ((wn << 6) + (g << 4) + vln) * 2);

    const __half* qk_base = g_qk16 + (size_t)(b * NT) * 4096 + h * ND;
    const __half* v_base = g_qkv16 + (size_t)(b * NT) * C3 + 4096 + h * ND;

#pragma unroll
    for (int i = 0; i < 4; i++) {
        int f = tid + (i << 8);
        int r = f >> 4;
        int seg = f & 15;
        cp_async16(smb + FB_Q + r * 272 + seg * 16,
                   (const char*)(qk_base + (size_t)(q0 + r) * 4096) + seg * 16);
        cp_async16(smb + FB_K(0) + r * 272 + seg * 16,
                   (const char*)(qk_base + 2048 + (size_t)r * 4096) + seg * 16);
        cp_async16(smb + FB_V(0) + r * 272 + seg * 16,
                   (const char*)(v_base + (size_t)r * C3) + seg * 16);
    }
    CP_COMMIT();

    float o[8][4];
#pragma unroll
    for (int j = 0; j < 8; j++)
#pragma unroll
        for (int e = 0; e < 4; e++) o[j][e] = 0.0f;
    float m0_ = -INFINITY, m1_ = -INFINITY, l0_ = 0.0f, l1_ = 0.0f;

    __half* Ph = (__half*)(smc + FB_P);
    float* redm = (float*)(smc + FB_RM);
    float* reds = (float*)(smc + FB_RS);

    for (int kt = 0; kt <= qb; kt++) {
        CP_WAIT0();
        __syncthreads();
        if (kt < qb) {
            const int k0n = (kt + 1) << 6;
            const int bufn = (kt + 1) & 1;
#pragma unroll
            for (int i = 0; i < 4; i++) {
                int f = tid + (i << 8);
                int r = f >> 4;
                int seg = f & 15;
                cp_async16(smb + FB_K(bufn) + r * 272 + seg * 16,
                           (const char*)(qk_base + 2048 + (size_t)(k0n + r) * 4096) + seg * 16);
                cp_async16(smb + FB_V(bufn) + r * 272 + seg * 16,
                           (const char*)(v_base + (size_t)(k0n + r) * C3) + seg * 16);
            }
            CP_COMMIT();
        }

        const int bufi = kt & 1;
        const uint32_t kstage = smb + FB_K(bufi);
        const uint32_t vstage = smb + FB_V(bufi);
        const int k0 = kt << 6;

        float s[4][4];
#pragma unroll
        for (int j = 0; j < 4; j++)
#pragma unroll
            for (int e = 0; e < 4; e++) s[j][e] = 0.0f;

#pragma unroll
        for (int c = 0; c < 8; c++) {
            const uint32_t cb = (uint32_t)(c << 5);
            uint32_t a0, a1, a2, a3;
            ldsm_x4(a0, a1, a2, a3, qoff + cb);
#pragma unroll
            for (int g = 0; g < 2; g++) {
                uint32_t b0, b1, b2, b3;
                ldsm_x4(b0, b1, b2, b3, kstage + koff[g] + cb);
                mma_f16(s[2 * g],     a0, a1, a2, a3, b0, b1);
                mma_f16(s[2 * g + 1], a0, a1, a2, a3, b2, b3);
            }
        }

        const int r0g = q0 + mbase + gid;
        const int r1g = r0g + 8;
        if (kt == qb) {
#pragma unroll
            for (int j = 0; j < 4; j++) {
                int cbase = k0 + (wn << 5) + (j << 3) + (tig << 1);
                s[j][0] = (cbase     <= r0g) ? s[j][0] * SM_SCALE : -1e30f;
                s[j][1] = (cbase + 1 <= r0g) ? s[j][1] * SM_SCALE : -1e30f;
                s[j][2] = (cbase     <= r1g) ? s[j][2] * SM_SCALE : -1e30f;
                s[j][3] = (cbase + 1 <= r1g) ? s[j][3] * SM_SCALE : -1e30f;
            }
        } else {
#pragma unroll
            for (int j = 0; j < 4; j++) {
                s[j][0] *= SM_SCALE; s[j][1] *= SM_SCALE;
                s[j][2] *= SM_SCALE; s[j][3] *= SM_SCALE;
            }
        }

        float pm0 = fmaxf(fmaxf(s[0][0], s[0][1]), fmaxf(s[1][0], s[1][1]));
        pm0 = fmaxf(pm0, fmaxf(fmaxf(s[2][0], s[2][1]), fmaxf(s[3][0], s[3][1])));
        float pm1 = fmaxf(fmaxf(s[0][2], s[0][3]), fmaxf(s[1][2], s[1][3]));
        pm1 = fmaxf(pm1, fmaxf(fmaxf(s[2][2], s[2][3]), fmaxf(s[3][2], s[3][3])));
        pm0 = fmaxf(pm0, __shfl_xor_sync(0xffffffffu, pm0, 1));
        pm0 = fmaxf(pm0, __shfl_xor_sync(0xffffffffu, pm0, 2));
        pm1 = fmaxf(pm1, __shfl_xor_sync(0xffffffffu, pm1, 1));
        pm1 = fmaxf(pm1, __shfl_xor_sync(0xffffffffu, pm1, 2));
        if (tig == 0) {
            redm[(wn << 6) + mbase + gid] = pm0;
            redm[(wn << 6) + mbase + gid + 8] = pm1;
        }
        __syncthreads();
        float mn0 = fmaxf(m0_, fmaxf(pm0, redm[((wn ^ 1) << 6) + mbase + gid]));
        float mn1 = fmaxf(m1_, fmaxf(pm1, redm[((wn ^ 1) << 6) + mbase + gid + 8]));
        float corr0 = __expf(m0_ - mn0);
        float corr1 = __expf(m1_ - mn1);

        float ps0 = 0.0f, ps1 = 0.0f;
#pragma unroll
        for (int j = 0; j < 4; j++) {
            float p00 = __expf(s[j][0] - mn0);
            float p01 = __expf(s[j][1] - mn0);
            float p10 = __expf(s[j][2] - mn1);
            float p11 = __expf(s[j][3] - mn1);
            ps0 += p00 + p01;
            ps1 += p10 + p11;
            int c = (wn << 5) + (j << 3) + (tig << 1);
            *(__half2*)&Ph[(mbase + gid) * 72 + c] = __floats2half2_rn(p00, p01);
            *(__half2*)&Ph[(mbase + gid + 8) * 72 + c] = __floats2half2_rn(p10, p11);
        }
        ps0 += __shfl_xor_sync(0xffffffffu, ps0, 1);
        ps0 += __shfl_xor_sync(0xffffffffu, ps0, 2);
        ps1 += __shfl_xor_sync(0xffffffffu, ps1, 1);
        ps1 += __shfl_xor_sync(0xffffffffu, ps1, 2);
        if (tig == 0) {
            reds[(wn << 6) + mbase + gid] = ps0;
            reds[(wn << 6) + mbase + gid + 8] = ps1;
        }
        __syncthreads();
        l0_ = l0_ * corr0 + ps0 + reds[((wn ^ 1) << 6) + mbase + gid];
        l1_ = l1_ * corr1 + ps1 + reds[((wn ^ 1) << 6) + mbase + gid + 8];
        m0_ = mn0; m1_ = mn1;
#pragma unroll
        for (int j = 0; j < 8; j++) {
            o[j][0] *= corr0; o[j][1] *= corr0;
            o[j][2] *= corr1; o[j][3] *= corr1;
        }

#pragma unroll
        for (int kb = 0; kb < 64; kb += 16) {
            uint32_t a0, a1, a2, a3;
            ldsm_x4(a0, a1, a2, a3, poff + (kb << 1));
#pragma unroll
            for (int g = 0; g < 4; g++) {
                uint32_t b0, b1, b2, b3;
                ldsm_x4_trans(b0, b1, b2, b3, vstage + voff[g] + kb * 272);
                mma_f16(o[2 * g],     a0, a1, a2, a3, b0, b1);
                mma_f16(o[2 * g + 1], a0, a1, a2, a3, b2, b3);
            }
        }
    }

    const float inv0 = 1.0f / l0_;
    const float inv1 = 1.0f / l1_;
    const int r0g = q0 + mbase + gid;
    __half* y0p = g_y16 + ((size_t)(b * NT) + r0g) * 2048 + h * ND;
    __half* y1p = y0p + (size_t)8 * 2048;
#pragma unroll
    for (int j = 0; j < 8; j++) {
        int c = (wn << 6) + (j << 3) + (tig << 1);
        *(__half2*)&y0p[c] = __floats2half2_rn(o[j][0] * inv0, o[j][1] * inv0);
        *(__half2*)&y1p[c] = __floats2half2_rn(o[j][2] * inv1, o[j][3] * inv1);
    }
}

// ============================================================
// launch
// ============================================================
extern "C" void kernel_launch(void* const* d_in, const int* in_sizes, int n_in,
                              void* d_out, int out_size)
{
    const float* x      = (const float*)d_in[0];
    const float* w_qkv  = (const float*)d_in[1];
    const float* w_proj = (const float*)d_in[2];
    const float* qw     = (const float*)d_in[3];
    const float* kw     = (const float*)d_in[4];
    float* out = (float*)d_out;

    __half* qkv16_ptr = nullptr;
    __half* x16_ptr = nullptr;
    __half* wqkvT16_ptr = nullptr;
    __half* wprojT16_ptr = nullptr;
    __half* y16_ptr = nullptr;
    cudaGetSymbolAddress((void**)&qkv16_ptr, g_qkv16);
    cudaGetSymbolAddress((void**)&x16_ptr, g_x16);
    cudaGetSymbolAddress((void**)&wqkvT16_ptr, g_wqkvT16);
    cudaGetSymbolAddress((void**)&wprojT16_ptr, g_wprojT16);
    cudaGetSymbolAddress((void**)&y16_ptr, g_y16);

    cudaFuncSetAttribute(gemm_f16_kernel<true>,
                         cudaFuncAttributeMaxDynamicSharedMemorySize, GB_SMEM_BYTES);
    cudaFuncSetAttribute(gemm_f16_kernel<false>,
                         cudaFuncAttributeMaxDynamicSharedMemorySize, GB_SMEM_BYTES);
    cudaFuncSetAttribute(flash_mma_kernel,
                         cudaFuncAttributeMaxDynamicSharedMemorySize, FB_SMEM_BYTES);

    // 1. RoPE tables
    rope_tables_kernel<<<(NT * 64 + 255) / 256, 256>>>();

    // 2. operand conversions
    {
        int n4 = BT * NC / 4;
        cvt16_kernel<<<(n4 + 255) / 256, 256>>>((const float4*)x, (uint2*)x16_ptr, n4);
        dim3 blk(32, 8);
        transpose16_kernel<<<dim3(C3 / 32, NC / 32), blk>>>(w_qkv, wqkvT16_ptr, NC, C3);
        transpose16_kernel<<<dim3(NC / 32, NC / 32), blk>>>(w_proj, wprojT16_ptr, NC, NC);
    }

    // 3. qkv = x @ w_qkv (fp16 mma, fp16 out)
    {
        dim3 grid(C3 / 256, BT / 128);
        gemm_f16_kernel<true><<<grid, 512, GB_SMEM_BYTES>>>(
            x16_ptr, wqkvT16_ptr, qkv16_ptr, NC, C3, 0);
    }

    // 4. RMSNorm + RoPE (q,k only; v already fp16 in place)
    rmsrope_kernel<<<BT, 256>>>(qw, kw);

    // 5. flash attention
    {
        dim3 grid(NT / 64, NB * NH);
        flash_mma_kernel<<<grid, 256, FB_SMEM_BYTES>>>();
    }

    // 6. out = y @ w_proj (fp16 mma, fp32 out)
    {
        dim3 grid(NC / 256, BT / 128);
        gemm_f16_kernel<false><<<grid, 512, GB_SMEM_BYTES>>>(
            y16_ptr, wprojT16_ptr, out, NC, NC, 0);
    }
}

// round 14
// speedup vs baseline: 1.0506x; 1.0506x over previous
#include <cuda_runtime.h>
#include <cuda_fp16.h>
#include <math.h>
#include <stdint.h>

// ---------------- problem constants ----------------
#define NB 2
#define NT 2048
#define NC 2048
#define NH 16
#define ND 128
#define C3 (3 * NC)      /* 6144 */
#define BT (NB * NT)     /* 4096 */

#define RMS_EPS 1.1920929e-07f
#define SM_SCALE (1.0f / 128.0f)

// ---------------- scratch ----------------
__device__ __half g_qkv16[(size_t)BT * C3];        // fp16 qkv straight from GEMM
__device__ __half g_x16[(size_t)BT * NC];          // x fp16
__device__ __half g_wqkvT16[(size_t)C3 * NC];      // w_qkv^T fp16
__device__ __half g_wprojT16[(size_t)NC * NC];     // w_proj^T fp16
__device__ __half g_qk16[(size_t)BT * 2 * NC];     // normed+roped q,k fp16
__device__ __half g_y16[(size_t)BT * NC];          // attention out fp16
__device__ float g_cos[NT * 64];
__device__ float g_sin[NT * 64];

// ---------------- helpers ----------------
__device__ __forceinline__ void mma_f16(float c[4],
                                        uint32_t a0, uint32_t a1, uint32_t a2, uint32_t a3,
                                        uint32_t b0, uint32_t b1) {
    asm volatile(
        "mma.sync.aligned.m16n8k16.row.col.f32.f16.f16.f32 "
        "{%0,%1,%2,%3}, {%4,%5,%6,%7}, {%8,%9}, {%0,%1,%2,%3};"
        : "+f"(c[0]), "+f"(c[1]), "+f"(c[2]), "+f"(c[3])
        : "r"(a0), "r"(a1), "r"(a2), "r"(a3), "r"(b0), "r"(b1));
}

__device__ __forceinline__ void ldsm_x4(uint32_t& r0, uint32_t& r1,
                                        uint32_t& r2, uint32_t& r3, uint32_t addr) {
    asm volatile("ldmatrix.sync.aligned.m8n8.x4.shared.b16 {%0,%1,%2,%3}, [%4];"
        : "=r"(r0), "=r"(r1), "=r"(r2), "=r"(r3) : "r"(addr));
}

__device__ __forceinline__ void ldsm_x4_trans(uint32_t& r0, uint32_t& r1,
                                              uint32_t& r2, uint32_t& r3, uint32_t addr) {
    asm volatile("ldmatrix.sync.aligned.m8n8.x4.trans.shared.b16 {%0,%1,%2,%3}, [%4];"
        : "=r"(r0), "=r"(r1), "=r"(r2), "=r"(r3) : "r"(addr));
}

__device__ __forceinline__ uint32_t smem_u32(const void* p) {
    uint32_t a;
    asm("{ .reg .u64 t; cvta.to.shared.u64 t, %1; cvt.u32.u64 %0, t; }"
        : "=r"(a) : "l"(p));
    return a;
}

__device__ __forceinline__ void cp_async16(uint32_t dst, const void* src) {
    asm volatile("cp.async.cg.shared.global [%0], [%1], 16;" :: "r"(dst), "l"(src));
}
#define CP_COMMIT() asm volatile("cp.async.commit_group;" ::: "memory")
#define CP_WAIT0()  asm volatile("cp.async.wait_group 0;" ::: "memory")
#define CP_WAIT1()  asm volatile("cp.async.wait_group 1;" ::: "memory")

// ============================================================
// RoPE tables
// ============================================================
__global__ void rope_tables_kernel() {
    int idx = blockIdx.x * blockDim.x + threadIdx.x;
    if (idx >= NT * 64) return;
    int t = idx >> 6;
    int i = idx & 63;
    double inv_f = exp(-((double)i / 64.0) * log(1.0e6));
    double ang = (double)t * inv_f;
    g_cos[idx] = (float)cos(ang);
    g_sin[idx] = (float)sin(ang);
}

// ============================================================
// fp32 -> fp16 copy
// ============================================================
__global__ __launch_bounds__(256) void cvt16_kernel(
    const float4* __restrict__ in, uint2* __restrict__ out, int n4)
{
    int i = blockIdx.x * blockDim.x + threadIdx.x;
    if (i >= n4) return;
    float4 v = in[i];
    __half2 lo = __floats2half2_rn(v.x, v.y);
    __half2 hi = __floats2half2_rn(v.z, v.w);
    uint2 p;
    p.x = *(uint32_t*)&lo;
    p.y = *(uint32_t*)&hi;
    out[i] = p;
}

// ============================================================
// Transpose -> fp16
// ============================================================
__global__ __launch_bounds__(256) void transpose16_kernel(
    const float* __restrict__ in, __half* __restrict__ out, int R, int Ccols)
{
    __shared__ float tile[32][33];
    int c0 = blockIdx.x * 32, r0 = blockIdx.y * 32;
    int tx = threadIdx.x, ty = threadIdx.y;
#pragma unroll
    for (int j = 0; j < 32; j += 8)
        tile[ty + j][tx] = in[(size_t)(r0 + ty + j) * Ccols + c0 + tx];
    __syncthreads();
#pragma unroll
    for (int j = 0; j < 32; j += 8)
        out[(size_t)(c0 + ty + j) * R + r0 + tx] = __float2half_rn(tile[tx][ty + j]);
}

// ============================================================
// fp16 mma GEMM (R11 geometry): C = A[M,K] @ Bt[N,K]^T.
// Block 128x256, BK=32, 256 thr = 8 warps (2m x 4n), warp 64x64,
// m16n8k16, 3-stage cp.async, ldmatrix frags.
// HALF_OUT selects fp16 vs fp32 epilogue.
// ============================================================
#define GB_STG_BYTES 30720
#define GB_SMEM_BYTES (3 * GB_STG_BYTES)

template <bool HALF_OUT>
__global__ __launch_bounds__(256, 1) void gemm_f16_kernel(
    const __half* __restrict__ A, const __half* __restrict__ Bt,
    void* __restrict__ Cm, int K, int ldC, int c0off)
{
    extern __shared__ float sm[];
    const uint32_t smb = smem_u32(sm);

    const int tid = threadIdx.x;
    const int wid = tid >> 5;
    const int lane = tid & 31;
    const int gid = lane >> 2;
    const int tig = lane & 3;
    const int warp_m = wid & 1;
    const int warp_n = wid >> 1;
    const int m0 = blockIdx.y << 7;
    const int n0 = blockIdx.x << 8;

    const int mbase = warp_m << 6;
    const int nbase = warp_n << 6;

    const int la16 = lane & 15;
    const int lha = lane >> 4;
    const int lb8 = lane & 7;
    const int lbg = (lane >> 4) & 1;
    const int lbh = (lane >> 3) & 1;

    uint32_t aoff[4], boff[4];
#pragma unroll
    for (int mf = 0; mf < 4; mf++)
        aoff[mf] = (uint32_t)((mbase + (mf << 4) + la16) * 80 + lha * 16);
#pragma unroll
    for (int g = 0; g < 4; g++)
        boff[g] = 10240u + (uint32_t)((nbase + (g << 4) + lb8 + (lbg << 3)) * 80 + lbh * 16);

    float acc[4][8][4];
#pragma unroll
    for (int i = 0; i < 4; i++)
#pragma unroll
        for (int j = 0; j < 8; j++)
#pragma unroll
            for (int e = 0; e < 4; e++) acc[i][j][e] = 0.0f;

    const int nt = K >> 5;

#define GB_ISSUE(t_)                                                          \
    do {                                                                      \
        const int _k0 = (t_) << 5;                                            \
        const uint32_t _sb = smb + ((t_) % 3) * GB_STG_BYTES;                 \
        _Pragma("unroll")                                                     \
        for (int _i = 0; _i < 2; _i++) {                                      \
            int _f = tid + (_i << 8);                                         \
            int _r = _f >> 2, _s = _f & 3;                                    \
            cp_async16(_sb + _r * 80 + _s * 16,                               \
                (const char*)A + (((size_t)(m0 + _r) * K + _k0) << 1) + _s * 16); \
        }                                                                     \
        _Pragma("unroll")                                                     \
        for (int _i = 0; _i < 4; _i++) {                                      \
            int _f = tid + (_i << 8);                                         \
            int _r = _f >> 2, _s = _f & 3;                                    \
            cp_async16(_sb + 10240 + _r * 80 + _s * 16,                       \
                (const char*)Bt + (((size_t)(n0 + _r) * K + _k0) << 1) + _s * 16); \
        }                                                                     \
    } while (0)

    GB_ISSUE(0); CP_COMMIT();
    GB_ISSUE(1); CP_COMMIT();

    for (int t = 0; t < nt; t++) {
        CP_WAIT1();
        __syncthreads();
        if (t + 2 < nt) GB_ISSUE(t + 2);
        CP_COMMIT();

        const uint32_t sb = smb + (t % 3) * GB_STG_BYTES;
#pragma unroll
        for (int c = 0; c < 2; c++) {
            const uint32_t cb = (uint32_t)(c << 5);
            uint32_t af[4][4];
#pragma unroll
            for (int mf = 0; mf < 4; mf++)
                ldsm_x4(af[mf][0], af[mf][1], af[mf][2], af[mf][3],
                        sb + aoff[mf] + cb);
            uint32_t bf[8][2];
#pragma unroll
            for (int g = 0; g < 4; g++) {
                uint32_t b0, b1, b2, b3;
                ldsm_x4(b0, b1, b2, b3, sb + boff[g] + cb);
                bf[2 * g][0] = b0; bf[2 * g][1] = b1;
                bf[2 * g + 1][0] = b2; bf[2 * g + 1][1] = b3;
            }
#pragma unroll
            for (int mf = 0; mf < 4; mf++)
#pragma unroll
                for (int nf = 0; nf < 8; nf++)
                    mma_f16(acc[mf][nf], af[mf][0], af[mf][1], af[mf][2], af[mf][3],
                            bf[nf][0], bf[nf][1]);
        }
    }
#undef GB_ISSUE

#pragma unroll
    for (int mf = 0; mf < 4; mf++) {
#pragma unroll
        for (int nf = 0; nf < 8; nf++) {
            int r0_ = m0 + mbase + (mf << 4) + gid;
            int c = c0off + n0 + nbase + (nf << 3) + (tig << 1);
            if (HALF_OUT) {
                __half* C = (__half*)Cm;
                *(__half2*)&C[(size_t)r0_ * ldC + c] =
                    __floats2half2_rn(acc[mf][nf][0], acc[mf][nf][1]);
                *(__half2*)&C[(size_t)(r0_ + 8) * ldC + c] =
                    __floats2half2_rn(acc[mf][nf][2], acc[mf][nf][3]);
            } else {
                float* C = (float*)Cm;
                *(float2*)&C[(size_t)r0_ * ldC + c] =
                    make_float2(acc[mf][nf][0], acc[mf][nf][1]);
                *(float2*)&C[(size_t)(r0_ + 8) * ldC + c] =
                    make_float2(acc[mf][nf][2], acc[mf][nf][3]);
            }
        }
    }
}

// ============================================================
// RMSNorm + RoPE: fp16 q,k in g_qkv16 -> fp16 g_qk16.
// v untouched (flash reads it from g_qkv16 directly).
// ============================================================
__global__ __launch_bounds__(256) void rmsrope_kernel(
    const float* __restrict__ qw, const float* __restrict__ kw)
{
    const int tok = blockIdx.x;
    const int t = tok & (NT - 1);
    const int warp = threadIdx.x >> 5;
    const int lane = threadIdx.x & 31;

    const float c0 = g_cos[t * 64 + lane];
    const float s0 = g_sin[t * 64 + lane];
    const float c1 = g_cos[t * 64 + 32 + lane];
    const float s1 = g_sin[t * 64 + 32 + lane];

#pragma unroll
    for (int s = 0; s < 4; s++) {
        int task = warp + (s << 3);
        int isK = task >> 4;
        int h = task & 15;
        const float* w = isK ? kw : qw;
        const __half* src = g_qkv16 + (size_t)tok * C3 + (size_t)isK * 2048 + (size_t)h * ND;

        float x0 = __half2float(src[lane]);
        float x1 = __half2float(src[lane + 32]);
        float x2 = __half2float(src[lane + 64]);
        float x3 = __half2float(src[lane + 96]);

        float ss = x0 * x0 + x1 * x1 + x2 * x2 + x3 * x3;
#pragma unroll
        for (int off = 16; off > 0; off >>= 1)
            ss += __shfl_xor_sync(0xffffffffu, ss, off);
        float inv = 1.0f / sqrtf(ss * (1.0f / (float)ND) + RMS_EPS);

        float n0 = x0 * inv * w[lane];
        float n1 = x1 * inv * w[lane + 32];
        float n2 = x2 * inv * w[lane + 64];
        float n3 = x3 * inv * w[lane + 96];

        __half* dst = g_qk16 + ((size_t)tok * 2 + isK) * 2048 + h * ND;
        dst[lane]      = __float2half_rn(n0 * c0 - n2 * s0);
        dst[lane + 32] = __float2half_rn(n1 * c1 - n3 * s1);
        dst[lane + 64] = __float2half_rn(n2 * c0 + n0 * s0);
        dst[lane + 96] = __float2half_rn(n3 * c1 + n1 * s1);
    }
}

// ============================================================
// Flash attention, all-fp16 MMA; V streamed from g_qkv16 (stride C3).
// ============================================================
#define FB_Q     0
#define FB_STG   34816
#define FB_K(s)  (17408 + (s) * FB_STG)
#define FB_V(s)  (17408 + (s) * FB_STG + 17408)
#define FB_P     87040
#define FB_RM    96256
#define FB_RS    96768
#define FB_SMEM_BYTES 97280

__global__ __launch_bounds__(256, 2) void flash_mma_kernel()
{
    extern __shared__ float sm[];
    char* smc = (char*)sm;
    const uint32_t smb = smem_u32(sm);

    const int tid = threadIdx.x;
    const int lane = tid & 31;
    const int wid = tid >> 5;
    const int gid = lane >> 2;
    const int tig = lane & 3;
    const int wm = wid & 3;
    const int wn = wid >> 2;
    const int mbase = wm << 4;

    const int qb = (int)gridDim.x - 1 - (int)blockIdx.x;
    const int bh = blockIdx.y;
    const int b = bh >> 4;
    const int h = bh & 15;
    const int q0 = qb << 6;

    const int la16 = lane & 15;
    const int lha = lane >> 4;
    const int lb8 = lane & 7;
    const int lbg = (lane >> 4) & 1;
    const int lbh = (lane >> 3) & 1;

    const uint32_t qoff = smb + FB_Q + (uint32_t)((mbase + la16) * 272 + lha * 16);
    uint32_t koff[2];
#pragma unroll
    for (int g = 0; g < 2; g++)
        koff[g] = (uint32_t)(((wn << 5) + (g << 4) + lb8 + (lbg << 3)) * 272 + lbh * 16);

    const uint32_t poff = smb + FB_P + (uint32_t)((mbase + la16) * 144 + lha * 16);

    const int vlk = (lane & 7) + (((lane >> 3) & 1) << 3);
    const int vln = ((lane >> 4) & 1) << 3;
    uint32_t voff[4];
#pragma unroll
    for (int g = 0; g < 4; g++)
        voff[g] = (uint32_t)(vlk * 272 + ((wn << 6) + (g << 4) + vln) * 2);

    const __half* qk_base = g_qk16 + (size_t)(b * NT) * 4096 + h * ND;
    const __half* v_base = g_qkv16 + (size_t)(b * NT) * C3 + 4096 + h * ND;

#pragma unroll
    for (int i = 0; i < 4; i++) {
        int f = tid + (i << 8);
        int r = f >> 4;
        int seg = f & 15;
        cp_async16(smb + FB_Q + r * 272 + seg * 16,
                   (const char*)(qk_base + (size_t)(q0 + r) * 4096) + seg * 16);
        cp_async16(smb + FB_K(0) + r * 272 + seg * 16,
                   (const char*)(qk_base + 2048 + (size_t)r * 4096) + seg * 16);
        cp_async16(smb + FB_V(0) + r * 272 + seg * 16,
                   (const char*)(v_base + (size_t)r * C3) + seg * 16);
    }
    CP_COMMIT();

    float o[8][4];
#pragma unroll
    for (int j = 0; j < 8; j++)
#pragma unroll
        for (int e = 0; e < 4; e++) o[j][e] = 0.0f;
    float m0_ = -INFINITY, m1_ = -INFINITY, l0_ = 0.0f, l1_ = 0.0f;

    __half* Ph = (__half*)(smc + FB_P);
    float* redm = (float*)(smc + FB_RM);
    float* reds = (float*)(smc + FB_RS);

    for (int kt = 0; kt <= qb; kt++) {
        CP_WAIT0();
        __syncthreads();
        if (kt < qb) {
            const int k0n = (kt + 1) << 6;
            const int bufn = (kt + 1) & 1;
#pragma unroll
            for (int i = 0; i < 4; i++) {
                int f = tid + (i << 8);
                int r = f >> 4;
                int seg = f & 15;
                cp_async16(smb + FB_K(bufn) + r * 272 + seg * 16,
                           (const char*)(qk_base + 2048 + (size_t)(k0n + r) * 4096) + seg * 16);
                cp_async16(smb + FB_V(bufn) + r * 272 + seg * 16,
                           (const char*)(v_base + (size_t)(k0n + r) * C3) + seg * 16);
            }
            CP_COMMIT();
        }

        const int bufi = kt & 1;
        const uint32_t kstage = smb + FB_K(bufi);
        const uint32_t vstage = smb + FB_V(bufi);
        const int k0 = kt << 6;

        float s[4][4];
#pragma unroll
        for (int j = 0; j < 4; j++)
#pragma unroll
            for (int e = 0; e < 4; e++) s[j][e] = 0.0f;

#pragma unroll
        for (int c = 0; c < 8; c++) {
            const uint32_t cb = (uint32_t)(c << 5);
            uint32_t a0, a1, a2, a3;
            ldsm_x4(a0, a1, a2, a3, qoff + cb);
#pragma unroll
            for (int g = 0; g < 2; g++) {
                uint32_t b0, b1, b2, b3;
                ldsm_x4(b0, b1, b2, b3, kstage + koff[g] + cb);
                mma_f16(s[2 * g],     a0, a1, a2, a3, b0, b1);
                mma_f16(s[2 * g + 1], a0, a1, a2, a3, b2, b3);
            }
        }

        const int r0g = q0 + mbase + gid;
        const int r1g = r0g + 8;
        if (kt == qb) {
#pragma unroll
            for (int j = 0; j < 4; j++) {
                int cbase = k0 + (wn << 5) + (j << 3) + (tig << 1);
                s[j][0] = (cbase     <= r0g) ? s[j][0] * SM_SCALE : -1e30f;
                s[j][1] = (cbase + 1 <= r0g) ? s[j][1] * SM_SCALE : -1e30f;
                s[j][2] = (cbase     <= r1g) ? s[j][2] * SM_SCALE : -1e30f;
                s[j][3] = (cbase + 1 <= r1g) ? s[j][3] * SM_SCALE : -1e30f;
            }
        } else {
#pragma unroll
            for (int j = 0; j < 4; j++) {
                s[j][0] *= SM_SCALE; s[j][1] *= SM_SCALE;
                s[j][2] *= SM_SCALE; s[j][3] *= SM_SCALE;
            }
        }

        float pm0 = fmaxf(fmaxf(s[0][0], s[0][1]), fmaxf(s[1][0], s[1][1]));
        pm0 = fmaxf(pm0, fmaxf(fmaxf(s[2][0], s[2][1]), fmaxf(s[3][0], s[3][1])));
        float pm1 = fmaxf(fmaxf(s[0][2], s[0][3]), fmaxf(s[1][2], s[1][3]));
        pm1 = fmaxf(pm1, fmaxf(fmaxf(s[2][2], s[2][3]), fmaxf(s[3][2], s[3][3])));
        pm0 = fmaxf(pm0, __shfl_xor_sync(0xffffffffu, pm0, 1));
        pm0 = fmaxf(pm0, __shfl_xor_sync(0xffffffffu, pm0, 2));
        pm1 = fmaxf(pm1, __shfl_xor_sync(0xffffffffu, pm1, 1));
        pm1 = fmaxf(pm1, __shfl_xor_sync(0xffffffffu, pm1, 2));
        if (tig == 0) {
            redm[(wn << 6) + mbase + gid] = pm0;
            redm[(wn << 6) + mbase + gid + 8] = pm1;
        }
        __syncthreads();
        float mn0 = fmaxf(m0_, fmaxf(pm0, redm[((wn ^ 1) << 6) + mbase + gid]));
        float mn1 = fmaxf(m1_, fmaxf(pm1, redm[((wn ^ 1) << 6) + mbase + gid + 8]));
        float corr0 = __expf(m0_ - mn0);
        float corr1 = __expf(m1_ - mn1);

        float ps0 = 0.0f, ps1 = 0.0f;
#pragma unroll
        for (int j = 0; j < 4; j++) {
            float p00 = __expf(s[j][0] - mn0);
            float p01 = __expf(s[j][1] - mn0);
            float p10 = __expf(s[j][2] - mn1);
            float p11 = __expf(s[j][3] - mn1);
            ps0 += p00 + p01;
            ps1 += p10 + p11;
            int c = (wn << 5) + (j << 3) + (tig << 1);
            *(__half2*)&Ph[(mbase + gid) * 72 + c] = __floats2half2_rn(p00, p01);
            *(__half2*)&Ph[(mbase + gid + 8) * 72 + c] = __floats2half2_rn(p10, p11);
        }
        ps0 += __shfl_xor_sync(0xffffffffu, ps0, 1);
        ps0 += __shfl_xor_sync(0xffffffffu, ps0, 2);
        ps1 += __shfl_xor_sync(0xffffffffu, ps1, 1);
        ps1 += __shfl_xor_sync(0xffffffffu, ps1, 2);
        if (tig == 0) {
            reds[(wn << 6) + mbase + gid] = ps0;
            reds[(wn << 6) + mbase + gid + 8] = ps1;
        }
        __syncthreads();
        l0_ = l0_ * corr0 + ps0 + reds[((wn ^ 1) << 6) + mbase + gid];
        l1_ = l1_ * corr1 + ps1 + reds[((wn ^ 1) << 6) + mbase + gid + 8];
        m0_ = mn0; m1_ = mn1;
#pragma unroll
        for (int j = 0; j < 8; j++) {
            o[j][0] *= corr0; o[j][1] *= corr0;
            o[j][2] *= corr1; o[j][3] *= corr1;
        }

#pragma unroll
        for (int kb = 0; kb < 64; kb += 16) {
            uint32_t a0, a1, a2, a3;
            ldsm_x4(a0, a1, a2, a3, poff + (kb << 1));
#pragma unroll
            for (int g = 0; g < 4; g++) {
                uint32_t b0, b1, b2, b3;
                ldsm_x4_trans(b0, b1, b2, b3, vstage + voff[g] + kb * 272);
                mma_f16(o[2 * g],     a0, a1, a2, a3, b0, b1);
                mma_f16(o[2 * g + 1], a0, a1, a2, a3, b2, b3);
            }
        }
    }

    const float inv0 = 1.0f / l0_;
    const float inv1 = 1.0f / l1_;
    const int r0g = q0 + mbase + gid;
    __half* y0p = g_y16 + ((size_t)(b * NT) + r0g) * 2048 + h * ND;
    __half* y1p = y0p + (size_t)8 * 2048;
#pragma unroll
    for (int j = 0; j < 8; j++) {
        int c = (wn << 6) + (j << 3) + (tig << 1);
        *(__half2*)&y0p[c] = __floats2half2_rn(o[j][0] * inv0, o[j][1] * inv0);
        *(__half2*)&y1p[c] = __floats2half2_rn(o[j][2] * inv1, o[j][3] * inv1);
    }
}

// ============================================================
// launch
// ============================================================
extern "C" void kernel_launch(void* const* d_in, const int* in_sizes, int n_in,
                              void* d_out, int out_size)
{
    const float* x      = (const float*)d_in[0];
    const float* w_qkv  = (const float*)d_in[1];
    const float* w_proj = (const float*)d_in[2];
    const float* qw     = (const float*)d_in[3];
    const float* kw     = (const float*)d_in[4];
    float* out = (float*)d_out;

    __half* qkv16_ptr = nullptr;
    __half* x16_ptr = nullptr;
    __half* wqkvT16_ptr = nullptr;
    __half* wprojT16_ptr = nullptr;
    __half* y16_ptr = nullptr;
    cudaGetSymbolAddress((void**)&qkv16_ptr, g_qkv16);
    cudaGetSymbolAddress((void**)&x16_ptr, g_x16);
    cudaGetSymbolAddress((void**)&wqkvT16_ptr, g_wqkvT16);
    cudaGetSymbolAddress((void**)&wprojT16_ptr, g_wprojT16);
    cudaGetSymbolAddress((void**)&y16_ptr, g_y16);

    cudaFuncSetAttribute(gemm_f16_kernel<true>,
                         cudaFuncAttributeMaxDynamicSharedMemorySize, GB_SMEM_BYTES);
    cudaFuncSetAttribute(gemm_f16_kernel<false>,
                         cudaFuncAttributeMaxDynamicSharedMemorySize, GB_SMEM_BYTES);
    cudaFuncSetAttribute(flash_mma_kernel,
                         cudaFuncAttributeMaxDynamicSharedMemorySize, FB_SMEM_BYTES);

    // 1. RoPE tables
    rope_tables_kernel<<<(NT * 64 + 255) / 256, 256>>>();

    // 2. operand conversions
    {
        int n4 = BT * NC / 4;
        cvt16_kernel<<<(n4 + 255) / 256, 256>>>((const float4*)x, (uint2*)x16_ptr, n4);
        dim3 blk(32, 8);
        transpose16_kernel<<<dim3(C3 / 32, NC / 32), blk>>>(w_qkv, wqkvT16_ptr, NC, C3);
        transpose16_kernel<<<dim3(NC / 32, NC / 32), blk>>>(w_proj, wprojT16_ptr, NC, NC);
    }

    // 3. qkv = x @ w_qkv (fp16 mma, fp16 out)
    {
        dim3 grid(C3 / 256, BT / 128);
        gemm_f16_kernel<true><<<grid, 256, GB_SMEM_BYTES>>>(
            x16_ptr, wqkvT16_ptr, qkv16_ptr, NC, C3, 0);
    }

    // 4. RMSNorm + RoPE (q,k only; v already fp16 in place)
    rmsrope_kernel<<<BT, 256>>>(qw, kw);

    // 5. flash attention
    {
        dim3 grid(NT / 64, NB * NH);
        flash_mma_kernel<<<grid, 256, FB_SMEM_BYTES>>>();
    }

    // 6. out = y @ w_proj (fp16 mma, fp32 out)
    {
        dim3 grid(NC / 256, BT / 128);
        gemm_f16_kernel<false><<<grid, 256, GB_SMEM_BYTES>>>(
            y16_ptr, wprojT16_ptr, out, NC, NC, 0);
    }
}

// round 15
// speedup vs baseline: 1.0552x; 1.0045x over previous
#include <cuda_runtime.h>
#include <cuda_fp16.h>
#include <math.h>
#include <stdint.h>

// ---------------- problem constants ----------------
#define NB 2
#define NT 2048
#define NC 2048
#define NH 16
#define ND 128
#define C3 (3 * NC)      /* 6144 */
#define BT (NB * NT)     /* 4096 */

#define RMS_EPS 1.1920929e-07f
#define SM_SCALE (1.0f / 128.0f)

// ---------------- scratch ----------------
__device__ __half g_qkv16[(size_t)BT * C3];        // fp16 qkv straight from GEMM
__device__ __half g_x16[(size_t)BT * NC];          // x fp16
__device__ __half g_wqkvT16[(size_t)C3 * NC];      // w_qkv^T fp16
__device__ __half g_wprojT16[(size_t)NC * NC];     // w_proj^T fp16
__device__ __half g_qk16[(size_t)BT * 2 * NC];     // normed+roped q,k fp16
__device__ __half g_y16[(size_t)BT * NC];          // attention out fp16
__device__ float g_cos[NT * 64];
__device__ float g_sin[NT * 64];

// ---------------- helpers ----------------
__device__ __forceinline__ void mma_f16(float c[4],
                                        uint32_t a0, uint32_t a1, uint32_t a2, uint32_t a3,
                                        uint32_t b0, uint32_t b1) {
    asm volatile(
        "mma.sync.aligned.m16n8k16.row.col.f32.f16.f16.f32 "
        "{%0,%1,%2,%3}, {%4,%5,%6,%7}, {%8,%9}, {%0,%1,%2,%3};"
        : "+f"(c[0]), "+f"(c[1]), "+f"(c[2]), "+f"(c[3])
        : "r"(a0), "r"(a1), "r"(a2), "r"(a3), "r"(b0), "r"(b1));
}

__device__ __forceinline__ void ldsm_x4(uint32_t& r0, uint32_t& r1,
                                        uint32_t& r2, uint32_t& r3, uint32_t addr) {
    asm volatile("ldmatrix.sync.aligned.m8n8.x4.shared.b16 {%0,%1,%2,%3}, [%4];"
        : "=r"(r0), "=r"(r1), "=r"(r2), "=r"(r3) : "r"(addr));
}

__device__ __forceinline__ void ldsm_x4_trans(uint32_t& r0, uint32_t& r1,
                                              uint32_t& r2, uint32_t& r3, uint32_t addr) {
    asm volatile("ldmatrix.sync.aligned.m8n8.x4.trans.shared.b16 {%0,%1,%2,%3}, [%4];"
        : "=r"(r0), "=r"(r1), "=r"(r2), "=r"(r3) : "r"(addr));
}

__device__ __forceinline__ uint32_t smem_u32(const void* p) {
    uint32_t a;
    asm("{ .reg .u64 t; cvta.to.shared.u64 t, %1; cvt.u32.u64 %0, t; }"
        : "=r"(a) : "l"(p));
    return a;
}

__device__ __forceinline__ void cp_async16(uint32_t dst, const void* src) {
    asm volatile("cp.async.cg.shared.global [%0], [%1], 16;" :: "r"(dst), "l"(src));
}
#define CP_COMMIT() asm volatile("cp.async.commit_group;" ::: "memory")
#define CP_WAIT0()  asm volatile("cp.async.wait_group 0;" ::: "memory")
#define CP_WAIT1()  asm volatile("cp.async.wait_group 1;" ::: "memory")

// ============================================================
// RoPE tables
// ============================================================
__global__ void rope_tables_kernel() {
    int idx = blockIdx.x * blockDim.x + threadIdx.x;
    if (idx >= NT * 64) return;
    int t = idx >> 6;
    int i = idx & 63;
    double inv_f = exp(-((double)i / 64.0) * log(1.0e6));
    double ang = (double)t * inv_f;
    g_cos[idx] = (float)cos(ang);
    g_sin[idx] = (float)sin(ang);
}

// ============================================================
// fp32 -> fp16 copy
// ============================================================
__global__ __launch_bounds__(256) void cvt16_kernel(
    const float4* __restrict__ in, uint2* __restrict__ out, int n4)
{
    int i = blockIdx.x * blockDim.x + threadIdx.x;
    if (i >= n4) return;
    float4 v = in[i];
    __half2 lo = __floats2half2_rn(v.x, v.y);
    __half2 hi = __floats2half2_rn(v.z, v.w);
    uint2 p;
    p.x = *(uint32_t*)&lo;
    p.y = *(uint32_t*)&hi;
    out[i] = p;
}

// ============================================================
// Transpose -> fp16
// ============================================================
__global__ __launch_bounds__(256) void transpose16_kernel(
    const float* __restrict__ in, __half* __restrict__ out, int R, int Ccols)
{
    __shared__ float tile[32][33];
    int c0 = blockIdx.x * 32, r0 = blockIdx.y * 32;
    int tx = threadIdx.x, ty = threadIdx.y;
#pragma unroll
    for (int j = 0; j < 32; j += 8)
        tile[ty + j][tx] = in[(size_t)(r0 + ty + j) * Ccols + c0 + tx];
    __syncthreads();
#pragma unroll
    for (int j = 0; j < 32; j += 8)
        out[(size_t)(c0 + ty + j) * R + r0 + tx] = __float2half_rn(tile[tx][ty + j]);
}

// ============================================================
// fp16 mma GEMM (proven R11/R13 geometry, UNCHANGED):
// Block 128x256, BK=32, 256 thr, warp 64x64, 3-stage cp.async.
// ============================================================
#define GB_STG_BYTES 30720
#define GB_SMEM_BYTES (3 * GB_STG_BYTES)

template <bool HALF_OUT>
__global__ __launch_bounds__(256, 1) void gemm_f16_kernel(
    const __half* __restrict__ A, const __half* __restrict__ Bt,
    void* __restrict__ Cm, int K, int ldC, int c0off)
{
    extern __shared__ float sm[];
    const uint32_t smb = smem_u32(sm);

    const int tid = threadIdx.x;
    const int wid = tid >> 5;
    const int lane = tid & 31;
    const int gid = lane >> 2;
    const int tig = lane & 3;
    const int warp_m = wid & 1;
    const int warp_n = wid >> 1;
    const int m0 = blockIdx.y << 7;
    const int n0 = blockIdx.x << 8;

    const int mbase = warp_m << 6;
    const int nbase = warp_n << 6;

    const int la16 = lane & 15;
    const int lha = lane >> 4;
    const int lb8 = lane & 7;
    const int lbg = (lane >> 4) & 1;
    const int lbh = (lane >> 3) & 1;

    uint32_t aoff[4], boff[4];
#pragma unroll
    for (int mf = 0; mf < 4; mf++)
        aoff[mf] = (uint32_t)((mbase + (mf << 4) + la16) * 80 + lha * 16);
#pragma unroll
    for (int g = 0; g < 4; g++)
        boff[g] = 10240u + (uint32_t)((nbase + (g << 4) + lb8 + (lbg << 3)) * 80 + lbh * 16);

    float acc[4][8][4];
#pragma unroll
    for (int i = 0; i < 4; i++)
#pragma unroll
        for (int j = 0; j < 8; j++)
#pragma unroll
            for (int e = 0; e < 4; e++) acc[i][j][e] = 0.0f;

    const int nt = K >> 5;

#define GB_ISSUE(t_)                                                          \
    do {                                                                      \
        const int _k0 = (t_) << 5;                                            \
        const uint32_t _sb = smb + ((t_) % 3) * GB_STG_BYTES;                 \
        _Pragma("unroll")                                                     \
        for (int _i = 0; _i < 2; _i++) {                                      \
            int _f = tid + (_i << 8);                                         \
            int _r = _f >> 2, _s = _f & 3;                                    \
            cp_async16(_sb + _r * 80 + _s * 16,                               \
                (const char*)A + (((size_t)(m0 + _r) * K + _k0) << 1) + _s * 16); \
        }                                                                     \
        _Pragma("unroll")                                                     \
        for (int _i = 0; _i < 4; _i++) {                                      \
            int _f = tid + (_i << 8);                                         \
            int _r = _f >> 2, _s = _f & 3;                                    \
            cp_async16(_sb + 10240 + _r * 80 + _s * 16,                       \
                (const char*)Bt + (((size_t)(n0 + _r) * K + _k0) << 1) + _s * 16); \
        }                                                                     \
    } while (0)

    GB_ISSUE(0); CP_COMMIT();
    GB_ISSUE(1); CP_COMMIT();

    for (int t = 0; t < nt; t++) {
        CP_WAIT1();
        __syncthreads();
        if (t + 2 < nt) GB_ISSUE(t + 2);
        CP_COMMIT();

        const uint32_t sb = smb + (t % 3) * GB_STG_BYTES;
#pragma unroll
        for (int c = 0; c < 2; c++) {
            const uint32_t cb = (uint32_t)(c << 5);
            uint32_t af[4][4];
#pragma unroll
            for (int mf = 0; mf < 4; mf++)
                ldsm_x4(af[mf][0], af[mf][1], af[mf][2], af[mf][3],
                        sb + aoff[mf] + cb);
            uint32_t bf[8][2];
#pragma unroll
            for (int g = 0; g < 4; g++) {
                uint32_t b0, b1, b2, b3;
                ldsm_x4(b0, b1, b2, b3, sb + boff[g] + cb);
                bf[2 * g][0] = b0; bf[2 * g][1] = b1;
                bf[2 * g + 1][0] = b2; bf[2 * g + 1][1] = b3;
            }
#pragma unroll
            for (int mf = 0; mf < 4; mf++)
#pragma unroll
                for (int nf = 0; nf < 8; nf++)
                    mma_f16(acc[mf][nf], af[mf][0], af[mf][1], af[mf][2], af[mf][3],
                            bf[nf][0], bf[nf][1]);
        }
    }
#undef GB_ISSUE

#pragma unroll
    for (int mf = 0; mf < 4; mf++) {
#pragma unroll
        for (int nf = 0; nf < 8; nf++) {
            int r0_ = m0 + mbase + (mf << 4) + gid;
            int c = c0off + n0 + nbase + (nf << 3) + (tig << 1);
            if (HALF_OUT) {
                __half* C = (__half*)Cm;
                *(__half2*)&C[(size_t)r0_ * ldC + c] =
                    __floats2half2_rn(acc[mf][nf][0], acc[mf][nf][1]);
                *(__half2*)&C[(size_t)(r0_ + 8) * ldC + c] =
                    __floats2half2_rn(acc[mf][nf][2], acc[mf][nf][3]);
            } else {
                float* C = (float*)Cm;
                *(float2*)&C[(size_t)r0_ * ldC + c] =
                    make_float2(acc[mf][nf][0], acc[mf][nf][1]);
                *(float2*)&C[(size_t)(r0_ + 8) * ldC + c] =
                    make_float2(acc[mf][nf][2], acc[mf][nf][3]);
            }
        }
    }
}

// ============================================================
// RMSNorm + RoPE: fp16 q,k in g_qkv16 -> fp16 g_qk16.
// ============================================================
__global__ __launch_bounds__(256) void rmsrope_kernel(
    const float* __restrict__ qw, const float* __restrict__ kw)
{
    const int tok = blockIdx.x;
    const int t = tok & (NT - 1);
    const int warp = threadIdx.x >> 5;
    const int lane = threadIdx.x & 31;

    const float c0 = g_cos[t * 64 + lane];
    const float s0 = g_sin[t * 64 + lane];
    const float c1 = g_cos[t * 64 + 32 + lane];
    const float s1 = g_sin[t * 64 + 32 + lane];

#pragma unroll
    for (int s = 0; s < 4; s++) {
        int task = warp + (s << 3);
        int isK = task >> 4;
        int h = task & 15;
        const float* w = isK ? kw : qw;
        const __half* src = g_qkv16 + (size_t)tok * C3 + (size_t)isK * 2048 + (size_t)h * ND;

        float x0 = __half2float(src[lane]);
        float x1 = __half2float(src[lane + 32]);
        float x2 = __half2float(src[lane + 64]);
        float x3 = __half2float(src[lane + 96]);

        float ss = x0 * x0 + x1 * x1 + x2 * x2 + x3 * x3;
#pragma unroll
        for (int off = 16; off > 0; off >>= 1)
            ss += __shfl_xor_sync(0xffffffffu, ss, off);
        float inv = 1.0f / sqrtf(ss * (1.0f / (float)ND) + RMS_EPS);

        float n0 = x0 * inv * w[lane];
        float n1 = x1 * inv * w[lane + 32];
        float n2 = x2 * inv * w[lane + 64];
        float n3 = x3 * inv * w[lane + 96];

        __half* dst = g_qk16 + ((size_t)tok * 2 + isK) * 2048 + h * ND;
        dst[lane]      = __float2half_rn(n0 * c0 - n2 * s0);
        dst[lane + 32] = __float2half_rn(n1 * c1 - n3 * s1);
        dst[lane + 64] = __float2half_rn(n2 * c0 + n0 * s0);
        dst[lane + 96] = __float2half_rn(n3 * c1 + n1 * s1);
    }
}

// ============================================================
// Flash attention v2: 128-row q tile, 8 warps x 16 rows each
// (warp owns complete S rows -> warp-local softmax, no cross-warp
// exchange). K tiles 64-wide, double-buffered cp.async.
// One __syncthreads per tile (stage sync); P is warp-private.
// smem: Q 128x272 | {K 64x272, V 64x272} x2 | P 128x144 = 122880 B
// ============================================================
#define FC_Q     0
#define FC_STG   34816
#define FC_K(s)  (34816 + (s) * FC_STG)
#define FC_V(s)  (34816 + (s) * FC_STG + 17408)
#define FC_P     104448
#define FC_SMEM_BYTES 122880

__global__ __launch_bounds__(256, 1) void flash_mma_kernel()
{
    extern __shared__ float sm[];
    char* smc = (char*)sm;
    const uint32_t smb = smem_u32(sm);

    const int tid = threadIdx.x;
    const int lane = tid & 31;
    const int wid = tid >> 5;
    const int gid = lane >> 2;
    const int tig = lane & 3;

    const int qb = (int)gridDim.x - 1 - (int)blockIdx.x;   // long blocks first
    const int bh = blockIdx.y;
    const int b = bh >> 4;
    const int h = bh & 15;
    const int q0 = qb << 7;          // 128-row q tile

    const int la16 = lane & 15;
    const int lha = lane >> 4;
    const int lb8 = lane & 7;
    const int lbg = (lane >> 4) & 1;
    const int lbh = (lane >> 3) & 1;

    // Q as A operand: warp's 16 rows
    const uint32_t qoff = smb + FC_Q + (uint32_t)((wid * 16 + la16) * 272 + lha * 16);
    // K as B operand (4 groups of 16 cols cover 64)
    uint32_t koff[4];
#pragma unroll
    for (int g = 0; g < 4; g++)
        koff[g] = (uint32_t)(((g << 4) + lb8 + (lbg << 3)) * 272 + lbh * 16);
    // P as A operand (warp-private rows, stride 144 B)
    const uint32_t poff = smb + FC_P + (uint32_t)((wid * 16 + la16) * 144 + lha * 16);
    // V as B operand via ldmatrix.trans (8 groups of 16 d-cols cover 128)
    const int vlk = (lane & 7) + (((lane >> 3) & 1) << 3);
    const int vln = ((lane >> 4) & 1) << 3;
    uint32_t voff[8];
#pragma unroll
    for (int g = 0; g < 8; g++)
        voff[g] = (uint32_t)(vlk * 272 + (((g << 4) + vln) << 1));

    const __half* qk_base = g_qk16 + (size_t)(b * NT) * 4096 + h * ND;
    const __half* v_base = g_qkv16 + (size_t)(b * NT) * C3 + 4096 + h * ND;

    // ---- prologue: Q (128 rows, 8 segs/thread) + K0/V0 (4 each) ----
#pragma unroll
    for (int i = 0; i < 8; i++) {
        int f = tid + (i << 8);
        int r = f >> 4;
        int seg = f & 15;
        cp_async16(smb + FC_Q + r * 272 + seg * 16,
                   (const char*)(qk_base + (size_t)(q0 + r) * 4096) + seg * 16);
    }
#pragma unroll
    for (int i = 0; i < 4; i++) {
        int f = tid + (i << 8);
        int r = f >> 4;
        int seg = f & 15;
        cp_async16(smb + FC_K(0) + r * 272 + seg * 16,
                   (const char*)(qk_base + 2048 + (size_t)r * 4096) + seg * 16);
        cp_async16(smb + FC_V(0) + r * 272 + seg * 16,
                   (const char*)(v_base + (size_t)r * C3) + seg * 16);
    }
    CP_COMMIT();

    float o[16][4];
#pragma unroll
    for (int j = 0; j < 16; j++)
#pragma unroll
        for (int e = 0; e < 4; e++) o[j][e] = 0.0f;
    float m0_ = -INFINITY, m1_ = -INFINITY, l0_ = 0.0f, l1_ = 0.0f;

    __half* Ph = (__half*)(smc + FC_P);
    const int prow0 = (wid << 4) + gid;

    const int nkt = (qb + 1) << 1;   // K tiles of 64 rows
    for (int kt = 0; kt < nkt; kt++) {
        CP_WAIT0();
        __syncthreads();
        if (kt + 1 < nkt) {
            const int k0n = (kt + 1) << 6;
            const int bufn = (kt + 1) & 1;
#pragma unroll
            for (int i = 0; i < 4; i++) {
                int f = tid + (i << 8);
                int r = f >> 4;
                int seg = f & 15;
                cp_async16(smb + FC_K(bufn) + r * 272 + seg * 16,
                           (const char*)(qk_base + 2048 + (size_t)(k0n + r) * 4096) + seg * 16);
                cp_async16(smb + FC_V(bufn) + r * 272 + seg * 16,
                           (const char*)(v_base + (size_t)(k0n + r) * C3) + seg * 16);
            }
            CP_COMMIT();
        }

        const int bufi = kt & 1;
        const uint32_t kstage = smb + FC_K(bufi);
        const uint32_t vstage = smb + FC_V(bufi);
        const int k0 = kt << 6;

        // ---- S = Q @ K^T (warp rows 16 x cols 64) ----
        float s[8][4];
#pragma unroll
        for (int j = 0; j < 8; j++)
#pragma unroll
            for (int e = 0; e < 4; e++) s[j][e] = 0.0f;

#pragma unroll
        for (int c = 0; c < 8; c++) {
            const uint32_t cb = (uint32_t)(c << 5);
            uint32_t a0, a1, a2, a3;
            ldsm_x4(a0, a1, a2, a3, qoff + cb);
#pragma unroll
            for (int g = 0; g < 4; g++) {
                uint32_t b0, b1, b2, b3;
                ldsm_x4(b0, b1, b2, b3, kstage + koff[g] + cb);
                mma_f16(s[2 * g],     a0, a1, a2, a3, b0, b1);
                mma_f16(s[2 * g + 1], a0, a1, a2, a3, b2, b3);
            }
        }

        // ---- scale + causal mask (masked only when k0 >= q0) ----
        const int r0g = q0 + prow0;
        const int r1g = r0g + 8;
        if (k0 >= q0) {
#pragma unroll
            for (int j = 0; j < 8; j++) {
                int cbase = k0 + (j << 3) + (tig << 1);
                s[j][0] = (cbase     <= r0g) ? s[j][0] * SM_SCALE : -1e30f;
                s[j][1] = (cbase + 1 <= r0g) ? s[j][1] * SM_SCALE : -1e30f;
                s[j][2] = (cbase     <= r1g) ? s[j][2] * SM_SCALE : -1e30f;
                s[j][3] = (cbase + 1 <= r1g) ? s[j][3] * SM_SCALE : -1e30f;
            }
        } else {
#pragma unroll
            for (int j = 0; j < 8; j++) {
                s[j][0] *= SM_SCALE; s[j][1] *= SM_SCALE;
                s[j][2] *= SM_SCALE; s[j][3] *= SM_SCALE;
            }
        }

        // ---- warp-local online softmax (quad shuffles only) ----
        float pm0 = -1e30f, pm1 = -1e30f;
#pragma unroll
        for (int j = 0; j < 8; j++) {
            pm0 = fmaxf(pm0, fmaxf(s[j][0], s[j][1]));
            pm1 = fmaxf(pm1, fmaxf(s[j][2], s[j][3]));
        }
        pm0 = fmaxf(pm0, __shfl_xor_sync(0xffffffffu, pm0, 1));
        pm0 = fmaxf(pm0, __shfl_xor_sync(0xffffffffu, pm0, 2));
        pm1 = fmaxf(pm1, __shfl_xor_sync(0xffffffffu, pm1, 1));
        pm1 = fmaxf(pm1, __shfl_xor_sync(0xffffffffu, pm1, 2));
        float mn0 = fmaxf(m0_, pm0);
        float mn1 = fmaxf(m1_, pm1);
        float corr0 = __expf(m0_ - mn0);
        float corr1 = __expf(m1_ - mn1);

        float ps0 = 0.0f, ps1 = 0.0f;
#pragma unroll
        for (int j = 0; j < 8; j++) {
            float p00 = __expf(s[j][0] - mn0);
            float p01 = __expf(s[j][1] - mn0);
            float p10 = __expf(s[j][2] - mn1);
            float p11 = __expf(s[j][3] - mn1);
            ps0 += p00 + p01;
            ps1 += p10 + p11;
            int c = (j << 3) + (tig << 1);
            *(__half2*)&Ph[prow0 * 72 + c] = __floats2half2_rn(p00, p01);
            *(__half2*)&Ph[(prow0 + 8) * 72 + c] = __floats2half2_rn(p10, p11);
        }
        ps0 += __shfl_xor_sync(0xffffffffu, ps0, 1);
        ps0 += __shfl_xor_sync(0xffffffffu, ps0, 2);
        ps1 += __shfl_xor_sync(0xffffffffu, ps1, 1);
        ps1 += __shfl_xor_sync(0xffffffffu, ps1, 2);
        l0_ = l0_ * corr0 + ps0;
        l1_ = l1_ * corr1 + ps1;
        m0_ = mn0; m1_ = mn1;
#pragma unroll
        for (int j = 0; j < 16; j++) {
            o[j][0] *= corr0; o[j][1] *= corr0;
            o[j][2] *= corr1; o[j][3] *= corr1;
        }
        __syncwarp();   // P stores visible to warp's ldmatrix

        // ---- O += P @ V (warp rows 16 x d 128; V via ldmatrix.trans) ----
#pragma unroll
        for (int kb = 0; kb < 64; kb += 16) {
            uint32_t a0, a1, a2, a3;
            ldsm_x4(a0, a1, a2, a3, poff + (kb << 1));
#pragma unroll
            for (int g = 0; g < 8; g++) {
                uint32_t b0, b1, b2, b3;
                ldsm_x4_trans(b0, b1, b2, b3, vstage + voff[g] + kb * 272);
                mma_f16(o[2 * g],     a0, a1, a2, a3, b0, b1);
                mma_f16(o[2 * g + 1], a0, a1, a2, a3, b2, b3);
            }
        }
        __syncwarp();   // P reads done before next tile's stores
    }

    // ---- epilogue: fp16 y ----
    const float inv0 = 1.0f / l0_;
    const float inv1 = 1.0f / l1_;
    const int r0g = q0 + prow0;
    __half* y0p = g_y16 + ((size_t)(b * NT) + r0g) * 2048 + h * ND;
    __half* y1p = y0p + (size_t)8 * 2048;
#pragma unroll
    for (int j = 0; j < 16; j++) {
        int c = (j << 3) + (tig << 1);
        *(__half2*)&y0p[c] = __floats2half2_rn(o[j][0] * inv0, o[j][1] * inv0);
        *(__half2*)&y1p[c] = __floats2half2_rn(o[j][2] * inv1, o[j][3] * inv1);
    }
}

// ============================================================
// launch
// ============================================================
extern "C" void kernel_launch(void* const* d_in, const int* in_sizes, int n_in,
                              void* d_out, int out_size)
{
    const float* x      = (const float*)d_in[0];
    const float* w_qkv  = (const float*)d_in[1];
    const float* w_proj = (const float*)d_in[2];
    const float* qw     = (const float*)d_in[3];
    const float* kw     = (const float*)d_in[4];
    float* out = (float*)d_out;

    __half* qkv16_ptr = nullptr;
    __half* x16_ptr = nullptr;
    __half* wqkvT16_ptr = nullptr;
    __half* wprojT16_ptr = nullptr;
    __half* y16_ptr = nullptr;
    cudaGetSymbolAddress((void**)&qkv16_ptr, g_qkv16);
    cudaGetSymbolAddress((void**)&x16_ptr, g_x16);
    cudaGetSymbolAddress((void**)&wqkvT16_ptr, g_wqkvT16);
    cudaGetSymbolAddress((void**)&wprojT16_ptr, g_wprojT16);
    cudaGetSymbolAddress((void**)&y16_ptr, g_y16);

    cudaFuncSetAttribute(gemm_f16_kernel<true>,
                         cudaFuncAttributeMaxDynamicSharedMemorySize, GB_SMEM_BYTES);
    cudaFuncSetAttribute(gemm_f16_kernel<false>,
                         cudaFuncAttributeMaxDynamicSharedMemorySize, GB_SMEM_BYTES);
    cudaFuncSetAttribute(flash_mma_kernel,
                         cudaFuncAttributeMaxDynamicSharedMemorySize, FC_SMEM_BYTES);

    // 1. RoPE tables
    rope_tables_kernel<<<(NT * 64 + 255) / 256, 256>>>();

    // 2. operand conversions
    {
        int n4 = BT * NC / 4;
        cvt16_kernel<<<(n4 + 255) / 256, 256>>>((const float4*)x, (uint2*)x16_ptr, n4);
        dim3 blk(32, 8);
        transpose16_kernel<<<dim3(C3 / 32, NC / 32), blk>>>(w_qkv, wqkvT16_ptr, NC, C3);
        transpose16_kernel<<<dim3(NC / 32, NC / 32), blk>>>(w_proj, wprojT16_ptr, NC, NC);
    }

    // 3. qkv = x @ w_qkv (fp16 mma, fp16 out)
    {
        dim3 grid(C3 / 256, BT / 128);
        gemm_f16_kernel<true><<<grid, 256, GB_SMEM_BYTES>>>(
            x16_ptr, wqkvT16_ptr, qkv16_ptr, NC, C3, 0);
    }

    // 4. RMSNorm + RoPE (q,k only; v already fp16 in place)
    rmsrope_kernel<<<BT, 256>>>(qw, kw);

    // 5. flash attention (128-row q tiles, warp-local softmax)
    {
        dim3 grid(NT / 128, NB * NH);
        flash_mma_kernel<<<grid, 256, FC_SMEM_BYTES>>>();
    }

    // 6. out = y @ w_proj (fp16 mma, fp32 out)
    {
        dim3 grid(NC / 256, BT / 128);
        gemm_f16_kernel<false><<<grid, 256, GB_SMEM_BYTES>>>(
            y16_ptr, wprojT16_ptr, out, NC, NC, 0);
    }
}